// round 5
// baseline (speedup 1.0000x reference)
#include <cuda_runtime.h>
#include <cfloat>

#define Bc 8
#define Np 4096
#define C1c 64
#define C2c 128
#define C3c 256

// ---------------- scratch (static __device__, no allocs) ----------------
__device__ float g_X1[Bc * C1c * Np];                 // 8 MB
__device__ float g_X2[Bc * C2c * Np];                 // 16 MB
__device__ float g_X3[Bc * C3c * Np];                 // 32 MB  (F, channel-major)
__device__ float g_Ft[Bc * Np * C3c];                 // 32 MB  (F transpose, point-major)
__device__ float g_sq[Bc * Np];
__device__ float g_G[(size_t)Bc * Np * Np];           // 512 MB (all-batch Gram)
__device__ float g_E[Bc * Np * C3c];                  // 32 MB  (edge features, point-major)
__device__ float g_poolp[Bc * 16 * C3c];              // pooling partials

// ---------------- conv 1x1 as GEMM ----------------
template <int L>
__global__ __launch_bounds__(256) void conv_gemm(const float* __restrict__ Xin,
                                                 const float* __restrict__ W,
                                                 const float* __restrict__ bias)
{
    constexpr int Cin  = (L == 0) ? 3  : (L == 1) ? 64  : 128;
    const float* X = (L == 0) ? Xin : (L == 1) ? g_X1 : g_X2;
    float*       Y = (L == 0) ? g_X1 : (L == 1) ? g_X2 : g_X3;

    const int b  = blockIdx.z;
    const int m0 = blockIdx.y * 64;
    const int n0 = blockIdx.x * 128;
    const float* Xb = X + (size_t)b * Cin * Np;
    float*       Yb = Y + (size_t)b * ((L == 0) ? 64 : (L == 1) ? 128 : 256) * Np;

    __shared__ float Ws[16][64];
    __shared__ float Xs[16][128];

    const int tid = threadIdx.x;
    const int tx = tid & 15;
    const int ty = tid >> 4;

    float acc[4][8];
#pragma unroll
    for (int i = 0; i < 4; i++)
#pragma unroll
        for (int j = 0; j < 8; j++) acc[i][j] = 0.f;

    for (int k0 = 0; k0 < Cin; k0 += 16) {
        for (int i = tid; i < 64 * 16; i += 256) {
            int m = i >> 4, k = i & 15;
            Ws[k][m] = (k0 + k < Cin) ? W[(m0 + m) * Cin + k0 + k] : 0.f;
        }
        for (int i = tid; i < 16 * 128; i += 256) {
            int k = i >> 7, n = i & 127;
            Xs[k][n] = (k0 + k < Cin) ? Xb[(size_t)(k0 + k) * Np + n0 + n] : 0.f;
        }
        __syncthreads();
#pragma unroll
        for (int k = 0; k < 16; k++) {
            float a[4], bb[8];
#pragma unroll
            for (int i = 0; i < 4; i++) a[i] = Ws[k][ty * 4 + i];
#pragma unroll
            for (int j = 0; j < 8; j++) bb[j] = Xs[k][tx * 8 + j];
#pragma unroll
            for (int i = 0; i < 4; i++)
#pragma unroll
                for (int j = 0; j < 8; j++) acc[i][j] += a[i] * bb[j];
        }
        __syncthreads();
    }
#pragma unroll
    for (int i = 0; i < 4; i++) {
        float bi = bias[m0 + ty * 4 + i];
#pragma unroll
        for (int j = 0; j < 8; j++)
            Yb[(size_t)(m0 + ty * 4 + i) * Np + n0 + tx * 8 + j] = acc[i][j] + bi;
    }
}

// ---------------- LayerNorm over point axis + affine + relu, in place ----
template <int L>
__global__ __launch_bounds__(256) void ln_relu(const float* __restrict__ g,
                                               const float* __restrict__ be)
{
    float* X = (L == 0) ? g_X1 : (L == 1) ? g_X2 : g_X3;
    const size_t base = (size_t)blockIdx.x * Np;
    const int tid = threadIdx.x;

    float y[16];
    float s = 0.f;
#pragma unroll
    for (int i = 0; i < 16; i++) {
        y[i] = X[base + tid + i * 256];
        s += y[i];
    }
    __shared__ float red[8];
    __shared__ float smu, svar;
#pragma unroll
    for (int o = 16; o; o >>= 1) s += __shfl_xor_sync(0xffffffffu, s, o);
    if ((tid & 31) == 0) red[tid >> 5] = s;
    __syncthreads();
    if (tid == 0) {
        float t = 0.f;
#pragma unroll
        for (int i = 0; i < 8; i++) t += red[i];
        smu = t * (1.f / Np);
    }
    __syncthreads();
    const float mu = smu;
    float vs = 0.f;
#pragma unroll
    for (int i = 0; i < 16; i++) {
        float d = y[i] - mu;
        vs += d * d;
    }
#pragma unroll
    for (int o = 16; o; o >>= 1) vs += __shfl_xor_sync(0xffffffffu, vs, o);
    if ((tid & 31) == 0) red[tid >> 5] = vs;
    __syncthreads();
    if (tid == 0) {
        float t = 0.f;
#pragma unroll
        for (int i = 0; i < 8; i++) t += red[i];
        svar = t * (1.f / Np);
    }
    __syncthreads();
    const float rstd = rsqrtf(svar + 1e-5f);
#pragma unroll
    for (int i = 0; i < 16; i++) {
        int n = tid + i * 256;
        X[base + n] = fmaxf((y[i] - mu) * rstd * g[n] + be[n], 0.f);
    }
}

// ---------------- transpose X3 [b][c][n] -> Ft [b][n][c] ----------------
__global__ __launch_bounds__(256) void transpose_k()
{
    __shared__ float t[32][33];
    const int b  = blockIdx.z;
    const int n0 = blockIdx.x * 32;
    const int c0 = blockIdx.y * 32;
    const float* Xb = g_X3 + (size_t)b * C3c * Np;
    float*       Fb = g_Ft + (size_t)b * Np * C3c;
    for (int r = threadIdx.y; r < 32; r += 8)
        t[r][threadIdx.x] = Xb[(size_t)(c0 + r) * Np + n0 + threadIdx.x];
    __syncthreads();
    for (int r = threadIdx.y; r < 32; r += 8)
        Fb[(size_t)(n0 + r) * C3c + c0 + threadIdx.x] = t[threadIdx.x][r];
}

// ---------------- sq[b][n] = sum_c F^2 ----------------
__global__ __launch_bounds__(256) void sq_k()
{
    const int b = blockIdx.y;
    const int n = blockIdx.x * 256 + threadIdx.x;
    const float* Xb = g_X3 + (size_t)b * C3c * Np;
    float a = 0.f;
    for (int c = 0; c < C3c; c++) {
        float v = Xb[(size_t)c * Np + n];
        a += v * v;
    }
    g_sq[b * Np + n] = a;
}

// ---------------- Gram v4: split-tf32 (hi/lo error compensation), full grid ----
// x = hi + lo with hi=tf32(x), lo=tf32(x-hi).  G = hiA*hiB + hiA*loB + loA*hiB
// -> ~fp32 accuracy on the tensor pipe.
__device__ __forceinline__ unsigned int f2tf32(float x)
{
    unsigned int r;
    asm("cvt.rna.tf32.f32 %0, %1;" : "=r"(r) : "f"(x));
    return r;
}

#define SMS 132   // smem row stride in floats

__device__ __forceinline__ void mma_tf32(float* acc, const unsigned int* a,
                                         unsigned int b0, unsigned int b1)
{
    asm volatile(
        "mma.sync.aligned.m16n8k8.row.col.f32.tf32.tf32.f32 "
        "{%0,%1,%2,%3}, {%4,%5,%6,%7}, {%8,%9}, {%0,%1,%2,%3};\n"
        : "+f"(acc[0]), "+f"(acc[1]), "+f"(acc[2]), "+f"(acc[3])
        : "r"(a[0]), "r"(a[1]), "r"(a[2]), "r"(a[3]), "r"(b0), "r"(b1));
}

__global__ __launch_bounds__(256) void gram_tf32x2()
{
    const int b  = blockIdx.z;
    const int n0 = blockIdx.y * 128;
    const int m0 = blockIdx.x * 128;
    const float* F = g_X3 + (size_t)b * C3c * Np;
    float* Gb = g_G + (size_t)b * Np * Np;

    __shared__ unsigned int AsH[16 * SMS];
    __shared__ unsigned int AsL[16 * SMS];
    __shared__ unsigned int BsH[16 * SMS];
    __shared__ unsigned int BsL[16 * SMS];

    const int tid  = threadIdx.x;
    const int lane = tid & 31;
    const int wid  = tid >> 5;
    const int g8   = lane >> 2;
    const int tg   = lane & 3;
    const int nb   = (wid >> 2) * 64;
    const int mb   = (wid & 3) * 32;

    float acc[4][4][4];
#pragma unroll
    for (int i = 0; i < 4; i++)
#pragma unroll
        for (int j = 0; j < 4; j++)
#pragma unroll
            for (int r = 0; r < 4; r++) acc[i][j][r] = 0.f;

    for (int k0 = 0; k0 < C3c; k0 += 16) {
        for (int i = tid; i < 512; i += 256) {
            int k = i >> 5, c4 = i & 31;
            float4 av = *(const float4*)(F + (size_t)(k0 + k) * Np + n0 + c4 * 4);
            float4 bv = *(const float4*)(F + (size_t)(k0 + k) * Np + m0 + c4 * 4);
            uint4 ah, al, bh, bl;
            ah.x = f2tf32(av.x); al.x = f2tf32(av.x - __uint_as_float(ah.x));
            ah.y = f2tf32(av.y); al.y = f2tf32(av.y - __uint_as_float(ah.y));
            ah.z = f2tf32(av.z); al.z = f2tf32(av.z - __uint_as_float(ah.z));
            ah.w = f2tf32(av.w); al.w = f2tf32(av.w - __uint_as_float(ah.w));
            bh.x = f2tf32(bv.x); bl.x = f2tf32(bv.x - __uint_as_float(bh.x));
            bh.y = f2tf32(bv.y); bl.y = f2tf32(bv.y - __uint_as_float(bh.y));
            bh.z = f2tf32(bv.z); bl.z = f2tf32(bv.z - __uint_as_float(bh.z));
            bh.w = f2tf32(bv.w); bl.w = f2tf32(bv.w - __uint_as_float(bh.w));
            *(uint4*)(AsH + k * SMS + c4 * 4) = ah;
            *(uint4*)(AsL + k * SMS + c4 * 4) = al;
            *(uint4*)(BsH + k * SMS + c4 * 4) = bh;
            *(uint4*)(BsL + k * SMS + c4 * 4) = bl;
        }
        __syncthreads();
#pragma unroll
        for (int kk = 0; kk < 16; kk += 8) {
            unsigned int aH[4][4], aL[4][4];
#pragma unroll
            for (int ti = 0; ti < 4; ti++) {
                int col = nb + 16 * ti + g8;
                int r0 = (kk + tg) * SMS, r1 = (kk + tg + 4) * SMS;
                aH[ti][0] = AsH[r0 + col];     aL[ti][0] = AsL[r0 + col];
                aH[ti][1] = AsH[r0 + col + 8]; aL[ti][1] = AsL[r0 + col + 8];
                aH[ti][2] = AsH[r1 + col];     aL[ti][2] = AsL[r1 + col];
                aH[ti][3] = AsH[r1 + col + 8]; aL[ti][3] = AsL[r1 + col + 8];
            }
#pragma unroll
            for (int tj = 0; tj < 4; tj++) {
                int c = mb + 8 * tj + g8;
                int r0 = (kk + tg) * SMS, r1 = (kk + tg + 4) * SMS;
                unsigned int bH0 = BsH[r0 + c], bH1 = BsH[r1 + c];
                unsigned int bL0 = BsL[r0 + c], bL1 = BsL[r1 + c];
#pragma unroll
                for (int ti = 0; ti < 4; ti++) {
                    mma_tf32(acc[ti][tj], aH[ti], bH0, bH1);   // hi*hi
                    mma_tf32(acc[ti][tj], aH[ti], bL0, bL1);   // hi*lo
                    mma_tf32(acc[ti][tj], aL[ti], bH0, bH1);   // lo*hi
                }
            }
        }
        __syncthreads();
    }

#pragma unroll
    for (int ti = 0; ti < 4; ti++) {
#pragma unroll
        for (int tj = 0; tj < 4; tj++) {
            int row = n0 + nb + 16 * ti + g8;
            int col = m0 + mb + 8 * tj + 2 * tg;
            *(float2*)(Gb + (size_t)row * Np + col) =
                make_float2(acc[ti][tj][0], acc[ti][tj][1]);
            *(float2*)(Gb + (size_t)(row + 8) * Np + col) =
                make_float2(acc[ti][tj][2], acc[ti][tj][3]);
        }
    }
}

// ---------------- topk: u64 keys, warp-shuffle selection, all batches ----
__device__ __forceinline__ unsigned long long pack_key(float s, int m)
{
    unsigned int u = __float_as_uint(s);
    u ^= (u >> 31) ? 0xFFFFFFFFu : 0x80000000u;
    return ((unsigned long long)u << 32) | (unsigned int)m;
}

__global__ __launch_bounds__(128) void topk_edge()
{
    const int b   = blockIdx.y;
    const int n   = blockIdx.x;
    const int tid = threadIdx.x;
    const float4* sq4  = (const float4*)(g_sq + (size_t)b * Np);
    const float4* G4   = (const float4*)(g_G + (size_t)b * Np * Np + (size_t)n * Np);
    const float* Ftb   = g_Ft + (size_t)b * Np * C3c;
    float*       Eb    = g_E  + (size_t)b * Np * C3c;

    unsigned long long v[16];
#pragma unroll
    for (int i = 0; i < 16; i++) v[i] = 0xFFFFFFFFFFFFFFFFull;

    for (int m4 = tid; m4 < Np / 4; m4 += 128) {
        float4 g = G4[m4];
        float4 q = sq4[m4];
        float s0 = q.x - 2.f * g.x;
        float s1 = q.y - 2.f * g.y;
        float s2 = q.z - 2.f * g.z;
        float s3 = q.w - 2.f * g.w;
        unsigned long long ks[4] = {pack_key(s0, m4 * 4), pack_key(s1, m4 * 4 + 1),
                                    pack_key(s2, m4 * 4 + 2), pack_key(s3, m4 * 4 + 3)};
#pragma unroll
        for (int j = 0; j < 4; j++) {
            unsigned long long k = ks[j];
            if (k < v[15]) {
                int p = 15;
                while (p > 0 && v[p - 1] > k) { v[p] = v[p - 1]; --p; }
                v[p] = k;
            }
        }
    }

    __shared__ unsigned long long wmin[4];
    int nbr[16];
    int p = 0;
    const int lane = tid & 31;
    const int wid  = tid >> 5;
    for (int r = 0; r < 16; r++) {
        unsigned long long k = (p < 16) ? v[p] : 0xFFFFFFFFFFFFFFFFull;
#pragma unroll
        for (int o = 16; o; o >>= 1) {
            unsigned long long other = __shfl_xor_sync(0xffffffffu, k, o);
            if (other < k) k = other;
        }
        if (lane == 0) wmin[wid] = k;
        __syncthreads();
        unsigned long long bm = wmin[0];
        if (wmin[1] < bm) bm = wmin[1];
        if (wmin[2] < bm) bm = wmin[2];
        if (wmin[3] < bm) bm = wmin[3];
        nbr[r] = (int)(bm & 0xFFFFFFFFu);
        if (p < 16 && v[p] == bm) p++;
        __syncthreads();
    }

    for (int c = tid; c < C3c; c += 128) {
        float mx = -FLT_MAX;
#pragma unroll
        for (int k = 0; k < 16; k++)
            mx = fmaxf(mx, Ftb[(size_t)nbr[k] * C3c + c]);
        Eb[(size_t)n * C3c + c] = mx;
    }
}

// ---------------- pooling partials ----------------
__global__ __launch_bounds__(256) void pool1_k()
{
    const int b  = blockIdx.y;
    const int ch = blockIdx.x;
    const int c  = threadIdx.x;
    const float* Eb = g_E + (size_t)b * Np * C3c;
    float a = 0.f;
    for (int n = ch * 256; n < (ch + 1) * 256; n++)
        a += Eb[(size_t)n * C3c + c];
    g_poolp[(b * 16 + ch) * C3c + c] = a;
}

// ---------------- tiny MLP 256->128->64->1 ----------------
__global__ __launch_bounds__(256) void mlp_k(const float* __restrict__ gw0, const float* __restrict__ gb0,
                                             const float* __restrict__ gw1, const float* __restrict__ gb1,
                                             const float* __restrict__ gw2, const float* __restrict__ gb2,
                                             float* __restrict__ out)
{
    __shared__ float pooled[8][256];
    __shared__ float h1[8][128];
    __shared__ float h2[8][64];
    const int tid = threadIdx.x;

    for (int idx = tid; idx < 8 * 256; idx += 256) {
        int b = idx >> 8, c = idx & 255;
        float s = 0.f;
        for (int ch = 0; ch < 16; ch++) s += g_poolp[(b * 16 + ch) * C3c + c];
        pooled[b][c] = s * (1.f / Np);
    }
    __syncthreads();
    for (int idx = tid; idx < 8 * 128; idx += 256) {
        int b = idx >> 7, j = idx & 127;
        float s = gb0[j];
        for (int i = 0; i < 256; i++) s += pooled[b][i] * gw0[j * 256 + i];
        h1[b][j] = fmaxf(s, 0.f);
    }
    __syncthreads();
    for (int idx = tid; idx < 8 * 64; idx += 256) {
        int b = idx >> 6, j = idx & 63;
        float s = gb1[j];
        for (int i = 0; i < 128; i++) s += h1[b][i] * gw1[j * 128 + i];
        h2[b][j] = fmaxf(s, 0.f);
    }
    __syncthreads();
    if (tid < 8) {
        float s = gb2[0];
        for (int i = 0; i < 64; i++) s += h2[tid][i] * gw2[i];
        out[tid] = s;
    }
}

// ---------------- launch ----------------
extern "C" void kernel_launch(void* const* d_in, const int* in_sizes, int n_in,
                              void* d_out, int out_size)
{
    (void)in_sizes; (void)n_in; (void)out_size;
    const float* pc  = (const float*)d_in[0];
    const float* w0  = (const float*)d_in[1];
    const float* b0  = (const float*)d_in[2];
    const float* g0  = (const float*)d_in[3];
    const float* be0 = (const float*)d_in[4];
    const float* w1  = (const float*)d_in[5];
    const float* b1  = (const float*)d_in[6];
    const float* g1  = (const float*)d_in[7];
    const float* be1 = (const float*)d_in[8];
    const float* w2  = (const float*)d_in[9];
    const float* b2  = (const float*)d_in[10];
    const float* g2  = (const float*)d_in[11];
    const float* be2 = (const float*)d_in[12];
    const float* gw0 = (const float*)d_in[13];
    const float* gb0 = (const float*)d_in[14];
    const float* gw1 = (const float*)d_in[15];
    const float* gb1 = (const float*)d_in[16];
    const float* gw2 = (const float*)d_in[17];
    const float* gb2 = (const float*)d_in[18];
    float* out = (float*)d_out;

    conv_gemm<0><<<dim3(32, 1, Bc), 256>>>(pc, w0, b0);
    ln_relu<0><<<Bc * C1c, 256>>>(g0, be0);
    conv_gemm<1><<<dim3(32, 2, Bc), 256>>>(nullptr, w1, b1);
    ln_relu<1><<<Bc * C2c, 256>>>(g1, be1);
    conv_gemm<2><<<dim3(32, 4, Bc), 256>>>(nullptr, w2, b2);
    ln_relu<2><<<Bc * C3c, 256>>>(g2, be2);

    transpose_k<<<dim3(Np / 32, C3c / 32, Bc), dim3(32, 8)>>>();
    sq_k<<<dim3(Np / 256, Bc), 256>>>();

    gram_tf32x2<<<dim3(32, 32, Bc), 256>>>();   // split-tf32, fp32-accurate
    topk_edge<<<dim3(Np, Bc), 128>>>();

    pool1_k<<<dim3(16, Bc), 256>>>();
    mlp_k<<<1, 256>>>(gw0, gb0, gw1, gb1, gw2, gb2, out);
}

// round 7
// speedup vs baseline: 1.1468x; 1.1468x over previous
#include <cuda_runtime.h>
#include <cuda_fp16.h>
#include <cfloat>
#include <cstdint>

#define Bc 8
#define Np 4096
#define C1c 64
#define C2c 128
#define C3c 256

// ---------------- scratch (static __device__, no allocs) ----------------
__device__ float g_X1[Bc * C1c * Np];                 // 8 MB
__device__ float g_X2[Bc * C2c * Np];                 // 16 MB
__device__ float g_X3[Bc * C3c * Np];                 // 32 MB  (F, channel-major)
__device__ float g_Ft[Bc * Np * C3c];                 // 32 MB  (F transpose, point-major)
__device__ __half g_FtH[Bc * Np * C3c];               // 16 MB  (fp16 hi)
__device__ __half g_FtL[Bc * Np * C3c];               // 16 MB  (fp16 lo residual)
__device__ float g_sq[Bc * Np];
__device__ float g_G[(size_t)Bc * Np * Np];           // 512 MB (all-batch Gram)
__device__ float g_E[Bc * Np * C3c];                  // 32 MB  (edge features, point-major)
__device__ float g_poolp[Bc * 16 * C3c];              // pooling partials

// ---------------- conv 1x1 as GEMM ----------------
template <int L>
__global__ __launch_bounds__(256) void conv_gemm(const float* __restrict__ Xin,
                                                 const float* __restrict__ W,
                                                 const float* __restrict__ bias)
{
    constexpr int Cin  = (L == 0) ? 3  : (L == 1) ? 64  : 128;
    const float* X = (L == 0) ? Xin : (L == 1) ? g_X1 : g_X2;
    float*       Y = (L == 0) ? g_X1 : (L == 1) ? g_X2 : g_X3;

    const int b  = blockIdx.z;
    const int m0 = blockIdx.y * 64;
    const int n0 = blockIdx.x * 128;
    const float* Xb = X + (size_t)b * Cin * Np;
    float*       Yb = Y + (size_t)b * ((L == 0) ? 64 : (L == 1) ? 128 : 256) * Np;

    __shared__ float Ws[16][64];
    __shared__ float Xs[16][128];

    const int tid = threadIdx.x;
    const int tx = tid & 15;
    const int ty = tid >> 4;

    float acc[4][8];
#pragma unroll
    for (int i = 0; i < 4; i++)
#pragma unroll
        for (int j = 0; j < 8; j++) acc[i][j] = 0.f;

    for (int k0 = 0; k0 < Cin; k0 += 16) {
        for (int i = tid; i < 64 * 16; i += 256) {
            int m = i >> 4, k = i & 15;
            Ws[k][m] = (k0 + k < Cin) ? W[(m0 + m) * Cin + k0 + k] : 0.f;
        }
        for (int i = tid; i < 16 * 128; i += 256) {
            int k = i >> 7, n = i & 127;
            Xs[k][n] = (k0 + k < Cin) ? Xb[(size_t)(k0 + k) * Np + n0 + n] : 0.f;
        }
        __syncthreads();
#pragma unroll
        for (int k = 0; k < 16; k++) {
            float a[4], bb[8];
#pragma unroll
            for (int i = 0; i < 4; i++) a[i] = Ws[k][ty * 4 + i];
#pragma unroll
            for (int j = 0; j < 8; j++) bb[j] = Xs[k][tx * 8 + j];
#pragma unroll
            for (int i = 0; i < 4; i++)
#pragma unroll
                for (int j = 0; j < 8; j++) acc[i][j] += a[i] * bb[j];
        }
        __syncthreads();
    }
#pragma unroll
    for (int i = 0; i < 4; i++) {
        float bi = bias[m0 + ty * 4 + i];
#pragma unroll
        for (int j = 0; j < 8; j++)
            Yb[(size_t)(m0 + ty * 4 + i) * Np + n0 + tx * 8 + j] = acc[i][j] + bi;
    }
}

// ---------------- LayerNorm over point axis + affine + relu, in place ----
template <int L>
__global__ __launch_bounds__(256) void ln_relu(const float* __restrict__ g,
                                               const float* __restrict__ be)
{
    float* X = (L == 0) ? g_X1 : (L == 1) ? g_X2 : g_X3;
    const size_t base = (size_t)blockIdx.x * Np;
    const int tid = threadIdx.x;

    float y[16];
    float s = 0.f;
#pragma unroll
    for (int i = 0; i < 16; i++) {
        y[i] = X[base + tid + i * 256];
        s += y[i];
    }
    __shared__ float red[8];
    __shared__ float smu, svar;
#pragma unroll
    for (int o = 16; o; o >>= 1) s += __shfl_xor_sync(0xffffffffu, s, o);
    if ((tid & 31) == 0) red[tid >> 5] = s;
    __syncthreads();
    if (tid == 0) {
        float t = 0.f;
#pragma unroll
        for (int i = 0; i < 8; i++) t += red[i];
        smu = t * (1.f / Np);
    }
    __syncthreads();
    const float mu = smu;
    float vs = 0.f;
#pragma unroll
    for (int i = 0; i < 16; i++) {
        float d = y[i] - mu;
        vs += d * d;
    }
#pragma unroll
    for (int o = 16; o; o >>= 1) vs += __shfl_xor_sync(0xffffffffu, vs, o);
    if ((tid & 31) == 0) red[tid >> 5] = vs;
    __syncthreads();
    if (tid == 0) {
        float t = 0.f;
#pragma unroll
        for (int i = 0; i < 8; i++) t += red[i];
        svar = t * (1.f / Np);
    }
    __syncthreads();
    const float rstd = rsqrtf(svar + 1e-5f);
#pragma unroll
    for (int i = 0; i < 16; i++) {
        int n = tid + i * 256;
        X[base + n] = fmaxf((y[i] - mu) * rstd * g[n] + be[n], 0.f);
    }
}

// ---------------- transpose X3 [b][c][n] -> Ft [b][n][c] ----------------
__global__ __launch_bounds__(256) void transpose_k()
{
    __shared__ float t[32][33];
    const int b  = blockIdx.z;
    const int n0 = blockIdx.x * 32;
    const int c0 = blockIdx.y * 32;
    const float* Xb = g_X3 + (size_t)b * C3c * Np;
    float*       Fb = g_Ft + (size_t)b * Np * C3c;
    for (int r = threadIdx.y; r < 32; r += 8)
        t[r][threadIdx.x] = Xb[(size_t)(c0 + r) * Np + n0 + threadIdx.x];
    __syncthreads();
    for (int r = threadIdx.y; r < 32; r += 8)
        Fb[(size_t)(n0 + r) * C3c + c0 + threadIdx.x] = t[threadIdx.x][r];
}

// ---------------- fp16 hi/lo split of Ft ----------------
__global__ __launch_bounds__(256) void ftsplit_k()
{
    const size_t i4 = (size_t)blockIdx.x * 256 + threadIdx.x;   // float4 index
    float4 v = ((const float4*)g_Ft)[i4];
    __half h0 = __float2half_rn(v.x), h1 = __float2half_rn(v.y);
    __half h2 = __float2half_rn(v.z), h3 = __float2half_rn(v.w);
    __half l0 = __float2half_rn(v.x - __half2float(h0));
    __half l1 = __float2half_rn(v.y - __half2float(h1));
    __half l2 = __float2half_rn(v.z - __half2float(h2));
    __half l3 = __float2half_rn(v.w - __half2float(h3));
    ((__half2*)g_FtH)[i4 * 2]     = __halves2half2(h0, h1);
    ((__half2*)g_FtH)[i4 * 2 + 1] = __halves2half2(h2, h3);
    ((__half2*)g_FtL)[i4 * 2]     = __halves2half2(l0, l1);
    ((__half2*)g_FtL)[i4 * 2 + 1] = __halves2half2(l2, l3);
}

// ---------------- sq[b][n] = sum_c F^2 ----------------
__global__ __launch_bounds__(256) void sq_k()
{
    const int b = blockIdx.y;
    const int n = blockIdx.x * 256 + threadIdx.x;
    const float* Xb = g_X3 + (size_t)b * C3c * Np;
    float a = 0.f;
    for (int c = 0; c < C3c; c++) {
        float v = Xb[(size_t)c * Np + n];
        a += v * v;
    }
    g_sq[b * Np + n] = a;
}

// ---------------- Gram v6: fp16 m16n8k16 mma.sync, hi/lo 3-term split ----
// G[n][m] = sum_k Ft[n][k]*Ft[m][k].  CTA 128x128, 8 warps 2x4 (64x32 each),
// K chunks of 32 staged point-major in smem (straight row copies).
#define SMS2 40   // smem row stride in halves (80 B) -> conflict-free frag loads

__device__ __forceinline__ void mma_f16(float* acc, const uint32_t* a,
                                        uint32_t b0, uint32_t b1)
{
    asm volatile(
        "mma.sync.aligned.m16n8k16.row.col.f32.f16.f16.f32 "
        "{%0,%1,%2,%3}, {%4,%5,%6,%7}, {%8,%9}, {%0,%1,%2,%3};\n"
        : "+f"(acc[0]), "+f"(acc[1]), "+f"(acc[2]), "+f"(acc[3])
        : "r"(a[0]), "r"(a[1]), "r"(a[2]), "r"(a[3]), "r"(b0), "r"(b1));
}

__global__ __launch_bounds__(256) void gram_f16x2()
{
    const int b  = blockIdx.z;
    const int n0 = blockIdx.y * 128;
    const int m0 = blockIdx.x * 128;
    const __half* FH = g_FtH + (size_t)b * Np * C3c;
    const __half* FL = g_FtL + (size_t)b * Np * C3c;
    float* Gb = g_G + (size_t)b * Np * Np;

    __shared__ __half AsH[128 * SMS2];
    __shared__ __half AsL[128 * SMS2];
    __shared__ __half BsH[128 * SMS2];
    __shared__ __half BsL[128 * SMS2];

    const int tid  = threadIdx.x;
    const int lane = tid & 31;
    const int wid  = tid >> 5;
    const int g8   = lane >> 2;
    const int tg   = lane & 3;
    const int nb   = (wid >> 2) * 64;   // warp row offset (A)
    const int mb   = (wid & 3) * 32;    // warp col offset (B)

    float acc[4][4][4];
#pragma unroll
    for (int i = 0; i < 4; i++)
#pragma unroll
        for (int j = 0; j < 4; j++)
#pragma unroll
            for (int r = 0; r < 4; r++) acc[i][j][r] = 0.f;

    for (int k0 = 0; k0 < C3c; k0 += 32) {
        // fill: straight row copies, 32 halves (4 x uint4) per row per buffer
        for (int i = tid; i < 512; i += 256) {
            int r = i >> 2, v = i & 3;
            *(uint4*)(AsH + r * SMS2 + v * 8) =
                *(const uint4*)(FH + (size_t)(n0 + r) * C3c + k0 + v * 8);
            *(uint4*)(AsL + r * SMS2 + v * 8) =
                *(const uint4*)(FL + (size_t)(n0 + r) * C3c + k0 + v * 8);
            *(uint4*)(BsH + r * SMS2 + v * 8) =
                *(const uint4*)(FH + (size_t)(m0 + r) * C3c + k0 + v * 8);
            *(uint4*)(BsL + r * SMS2 + v * 8) =
                *(const uint4*)(FL + (size_t)(m0 + r) * C3c + k0 + v * 8);
        }
        __syncthreads();
#pragma unroll
        for (int kk = 0; kk < 32; kk += 16) {
            uint32_t aH[4][4], aL[4][4];
#pragma unroll
            for (int ti = 0; ti < 4; ti++) {
                int r0 = (nb + 16 * ti + g8) * SMS2 + kk + 2 * tg;
                int r1 = r0 + 8 * SMS2;
                aH[ti][0] = *(const uint32_t*)(AsH + r0);
                aH[ti][1] = *(const uint32_t*)(AsH + r1);
                aH[ti][2] = *(const uint32_t*)(AsH + r0 + 8);
                aH[ti][3] = *(const uint32_t*)(AsH + r1 + 8);
                aL[ti][0] = *(const uint32_t*)(AsL + r0);
                aL[ti][1] = *(const uint32_t*)(AsL + r1);
                aL[ti][2] = *(const uint32_t*)(AsL + r0 + 8);
                aL[ti][3] = *(const uint32_t*)(AsL + r1 + 8);
            }
#pragma unroll
            for (int tj = 0; tj < 4; tj++) {
                int c0 = (mb + 8 * tj + g8) * SMS2 + kk + 2 * tg;
                uint32_t bH0 = *(const uint32_t*)(BsH + c0);
                uint32_t bH1 = *(const uint32_t*)(BsH + c0 + 8);
                uint32_t bL0 = *(const uint32_t*)(BsL + c0);
                uint32_t bL1 = *(const uint32_t*)(BsL + c0 + 8);
#pragma unroll
                for (int ti = 0; ti < 4; ti++) {
                    mma_f16(acc[ti][tj], aH[ti], bH0, bH1);   // hi*hi
                    mma_f16(acc[ti][tj], aH[ti], bL0, bL1);   // hi*lo
                    mma_f16(acc[ti][tj], aL[ti], bH0, bH1);   // lo*hi
                }
            }
        }
        __syncthreads();
    }

#pragma unroll
    for (int ti = 0; ti < 4; ti++) {
#pragma unroll
        for (int tj = 0; tj < 4; tj++) {
            int row = n0 + nb + 16 * ti + g8;
            int col = m0 + mb + 8 * tj + 2 * tg;
            *(float2*)(Gb + (size_t)row * Np + col) =
                make_float2(acc[ti][tj][0], acc[ti][tj][1]);
            *(float2*)(Gb + (size_t)(row + 8) * Np + col) =
                make_float2(acc[ti][tj][2], acc[ti][tj][3]);
        }
    }
}

// ---------------- topk: u64 keys, warp-shuffle selection, all batches ----
__device__ __forceinline__ unsigned long long pack_key(float s, int m)
{
    unsigned int u = __float_as_uint(s);
    u ^= (u >> 31) ? 0xFFFFFFFFu : 0x80000000u;
    return ((unsigned long long)u << 32) | (unsigned int)m;
}

__global__ __launch_bounds__(128) void topk_edge()
{
    const int b   = blockIdx.y;
    const int n   = blockIdx.x;
    const int tid = threadIdx.x;
    const float4* sq4  = (const float4*)(g_sq + (size_t)b * Np);
    const float4* G4   = (const float4*)(g_G + (size_t)b * Np * Np + (size_t)n * Np);
    const float* Ftb   = g_Ft + (size_t)b * Np * C3c;
    float*       Eb    = g_E  + (size_t)b * Np * C3c;

    unsigned long long v[16];
#pragma unroll
    for (int i = 0; i < 16; i++) v[i] = 0xFFFFFFFFFFFFFFFFull;

    for (int m4 = tid; m4 < Np / 4; m4 += 128) {
        float4 g = G4[m4];
        float4 q = sq4[m4];
        float s0 = q.x - 2.f * g.x;
        float s1 = q.y - 2.f * g.y;
        float s2 = q.z - 2.f * g.z;
        float s3 = q.w - 2.f * g.w;
        unsigned long long ks[4] = {pack_key(s0, m4 * 4), pack_key(s1, m4 * 4 + 1),
                                    pack_key(s2, m4 * 4 + 2), pack_key(s3, m4 * 4 + 3)};
#pragma unroll
        for (int j = 0; j < 4; j++) {
            unsigned long long k = ks[j];
            if (k < v[15]) {
                int p = 15;
                while (p > 0 && v[p - 1] > k) { v[p] = v[p - 1]; --p; }
                v[p] = k;
            }
        }
    }

    __shared__ unsigned long long wmin[4];
    int nbr[16];
    int p = 0;
    const int lane = tid & 31;
    const int wid  = tid >> 5;
    for (int r = 0; r < 16; r++) {
        unsigned long long k = (p < 16) ? v[p] : 0xFFFFFFFFFFFFFFFFull;
#pragma unroll
        for (int o = 16; o; o >>= 1) {
            unsigned long long other = __shfl_xor_sync(0xffffffffu, k, o);
            if (other < k) k = other;
        }
        if (lane == 0) wmin[wid] = k;
        __syncthreads();
        unsigned long long bm = wmin[0];
        if (wmin[1] < bm) bm = wmin[1];
        if (wmin[2] < bm) bm = wmin[2];
        if (wmin[3] < bm) bm = wmin[3];
        nbr[r] = (int)(bm & 0xFFFFFFFFu);
        if (p < 16 && v[p] == bm) p++;
        __syncthreads();
    }

    for (int c = tid; c < C3c; c += 128) {
        float mx = -FLT_MAX;
#pragma unroll
        for (int k = 0; k < 16; k++)
            mx = fmaxf(mx, Ftb[(size_t)nbr[k] * C3c + c]);
        Eb[(size_t)n * C3c + c] = mx;
    }
}

// ---------------- pooling partials ----------------
__global__ __launch_bounds__(256) void pool1_k()
{
    const int b  = blockIdx.y;
    const int ch = blockIdx.x;
    const int c  = threadIdx.x;
    const float* Eb = g_E + (size_t)b * Np * C3c;
    float a = 0.f;
    for (int n = ch * 256; n < (ch + 1) * 256; n++)
        a += Eb[(size_t)n * C3c + c];
    g_poolp[(b * 16 + ch) * C3c + c] = a;
}

// ---------------- tiny MLP 256->128->64->1 ----------------
__global__ __launch_bounds__(256) void mlp_k(const float* __restrict__ gw0, const float* __restrict__ gb0,
                                             const float* __restrict__ gw1, const float* __restrict__ gb1,
                                             const float* __restrict__ gw2, const float* __restrict__ gb2,
                                             float* __restrict__ out)
{
    __shared__ float pooled[8][256];
    __shared__ float h1[8][128];
    __shared__ float h2[8][64];
    const int tid = threadIdx.x;

    for (int idx = tid; idx < 8 * 256; idx += 256) {
        int b = idx >> 8, c = idx & 255;
        float s = 0.f;
        for (int ch = 0; ch < 16; ch++) s += g_poolp[(b * 16 + ch) * C3c + c];
        pooled[b][c] = s * (1.f / Np);
    }
    __syncthreads();
    for (int idx = tid; idx < 8 * 128; idx += 256) {
        int b = idx >> 7, j = idx & 127;
        float s = gb0[j];
        for (int i = 0; i < 256; i++) s += pooled[b][i] * gw0[j * 256 + i];
        h1[b][j] = fmaxf(s, 0.f);
    }
    __syncthreads();
    for (int idx = tid; idx < 8 * 64; idx += 256) {
        int b = idx >> 6, j = idx & 63;
        float s = gb1[j];
        for (int i = 0; i < 128; i++) s += h1[b][i] * gw1[j * 128 + i];
        h2[b][j] = fmaxf(s, 0.f);
    }
    __syncthreads();
    if (tid < 8) {
        float s = gb2[0];
        for (int i = 0; i < 64; i++) s += h2[tid][i] * gw2[i];
        out[tid] = s;
    }
}

// ---------------- launch ----------------
extern "C" void kernel_launch(void* const* d_in, const int* in_sizes, int n_in,
                              void* d_out, int out_size)
{
    (void)in_sizes; (void)n_in; (void)out_size;
    const float* pc  = (const float*)d_in[0];
    const float* w0  = (const float*)d_in[1];
    const float* b0  = (const float*)d_in[2];
    const float* g0  = (const float*)d_in[3];
    const float* be0 = (const float*)d_in[4];
    const float* w1  = (const float*)d_in[5];
    const float* b1  = (const float*)d_in[6];
    const float* g1  = (const float*)d_in[7];
    const float* be1 = (const float*)d_in[8];
    const float* w2  = (const float*)d_in[9];
    const float* b2  = (const float*)d_in[10];
    const float* g2  = (const float*)d_in[11];
    const float* be2 = (const float*)d_in[12];
    const float* gw0 = (const float*)d_in[13];
    const float* gb0 = (const float*)d_in[14];
    const float* gw1 = (const float*)d_in[15];
    const float* gb1 = (const float*)d_in[16];
    const float* gw2 = (const float*)d_in[17];
    const float* gb2 = (const float*)d_in[18];
    float* out = (float*)d_out;

    conv_gemm<0><<<dim3(32, 1, Bc), 256>>>(pc, w0, b0);
    ln_relu<0><<<Bc * C1c, 256>>>(g0, be0);
    conv_gemm<1><<<dim3(32, 2, Bc), 256>>>(nullptr, w1, b1);
    ln_relu<1><<<Bc * C2c, 256>>>(g1, be1);
    conv_gemm<2><<<dim3(32, 4, Bc), 256>>>(nullptr, w2, b2);
    ln_relu<2><<<Bc * C3c, 256>>>(g2, be2);

    transpose_k<<<dim3(Np / 32, C3c / 32, Bc), dim3(32, 8)>>>();
    ftsplit_k<<<Bc * Np * C3c / 4 / 256, 256>>>();
    sq_k<<<dim3(Np / 256, Bc), 256>>>();

    gram_f16x2<<<dim3(32, 32, Bc), 256>>>();   // fp16 split, k16 mma
    topk_edge<<<dim3(Np, Bc), 128>>>();

    pool1_k<<<dim3(16, Bc), 256>>>();
    mlp_k<<<1, 256>>>(gw0, gb0, gw1, gb1, gw2, gb2, out);
}